// round 2
// baseline (speedup 1.0000x reference)
#include <cuda_runtime.h>
#include <math.h>

#define NN 50000
#define EE 1600000
#define DD 128
#define HC 64   // H*C = 2*32

// ---- scratch (device globals; no allocation allowed) ----
__device__ float g_xf[NN * DD];       // elu(x)                 25.6 MB
__device__ float g_h[NN * HC];        // h = xf @ W             12.8 MB
__device__ float g_asrc[NN * 2];
__device__ float g_adst[NN * 2];
__device__ float g_m[NN * 2];         // segment max (init = self-loop alpha)
__device__ float g_denom[NN * 2];
__device__ float g_rd[NN * 2];        // 1/denom
__device__ float g_ea[EE * 2];        // alpha, later exp(alpha-m)   12.8 MB
__device__ float g_nw[NN];
__device__ float g_cnt[NN];

__device__ __forceinline__ void atomicMaxF(float* addr, float v) {
    // order-preserving int/uint trick (valid for all sign combinations)
    if (v >= 0.0f) atomicMax((int*)addr, __float_as_int(v));
    else           atomicMin((unsigned int*)addr, __float_as_uint(v));
}

__device__ __forceinline__ float lrelu(float a) { return a > 0.0f ? a : 0.2f * a; }

__device__ __forceinline__ void fma4(float4& acc, const float4 wv, const float xs) {
    acc.x += xs * wv.x; acc.y += xs * wv.y; acc.z += xs * wv.z; acc.w += xs * wv.w;
}

// ---------------- 1) elu(x) ----------------
__global__ void k_elu(const float* __restrict__ x) {
    int i = blockIdx.x * blockDim.x + threadIdx.x;   // float4 index
    if (i >= NN * DD / 4) return;
    float4 v = ((const float4*)x)[i];
    v.x = v.x > 0.f ? v.x : expm1f(v.x);
    v.y = v.y > 0.f ? v.y : expm1f(v.y);
    v.z = v.z > 0.f ? v.z : expm1f(v.z);
    v.w = v.w > 0.f ? v.w : expm1f(v.w);
    ((float4*)g_xf)[i] = v;
}

// ---------------- 2) h = xf @ W  (W staged in smem, 32KB) ----------------
__global__ void k_gemm(const float* __restrict__ W) {
    __shared__ float sW[DD * HC];                 // [128][64] row-major, 32 KB
    int tid = threadIdx.x;                        // 256 threads
    const float4* Wv = (const float4*)W;
    float4* sWv = (float4*)sW;
#pragma unroll
    for (int i = 0; i < 8; i++) sWv[tid + i * 256] = Wv[tid + i * 256];
    __syncthreads();

    int r  = tid >> 2;                            // 64 rows / block
    int cg = (tid & 3) << 4;                      // 16 cols / thread
    int gr = blockIdx.x * 64 + r;
    if (gr >= NN) return;

    float4 a0 = make_float4(0,0,0,0), a1 = a0, a2 = a0, a3 = a0;
    const float4* xp = (const float4*)(g_xf + (size_t)gr * DD);
#pragma unroll 4
    for (int k4 = 0; k4 < 32; k4++) {
        float4 xv = xp[k4];
#pragma unroll
        for (int j = 0; j < 4; j++) {
            float xs = (j == 0) ? xv.x : (j == 1) ? xv.y : (j == 2) ? xv.z : xv.w;
            const float4* wr = (const float4*)&sW[(k4 * 4 + j) * HC + cg];
            fma4(a0, wr[0], xs);
            fma4(a1, wr[1], xs);
            fma4(a2, wr[2], xs);
            fma4(a3, wr[3], xs);
        }
    }
    float4* op = (float4*)(g_h + (size_t)gr * HC + cg);
    op[0] = a0; op[1] = a1; op[2] = a2; op[3] = a3;
}

// ---------------- 3) per-node: a_src, a_dst, m = self-loop alpha ----------------
__global__ void k_node_prep(const float* __restrict__ att_src, const float* __restrict__ att_dst) {
    int n = blockIdx.x * blockDim.x + threadIdx.x;
    if (n >= NN) return;
    const float4* hp = (const float4*)(g_h + (size_t)n * HC);
    float as0 = 0, ad0 = 0, as1 = 0, ad1 = 0;
#pragma unroll
    for (int i = 0; i < 8; i++) {
        float4 h4 = hp[i];
        float4 s4 = ((const float4*)att_src)[i];
        float4 d4 = ((const float4*)att_dst)[i];
        as0 += h4.x*s4.x + h4.y*s4.y + h4.z*s4.z + h4.w*s4.w;
        ad0 += h4.x*d4.x + h4.y*d4.y + h4.z*d4.z + h4.w*d4.w;
    }
#pragma unroll
    for (int i = 8; i < 16; i++) {
        float4 h4 = hp[i];
        float4 s4 = ((const float4*)att_src)[i];
        float4 d4 = ((const float4*)att_dst)[i];
        as1 += h4.x*s4.x + h4.y*s4.y + h4.z*s4.z + h4.w*s4.w;
        ad1 += h4.x*d4.x + h4.y*d4.y + h4.z*d4.z + h4.w*d4.w;
    }
    g_asrc[2*n] = as0; g_asrc[2*n+1] = as1;
    g_adst[2*n] = ad0; g_adst[2*n+1] = ad1;
    g_m[2*n]   = lrelu(as0 + ad0);   // self-loop alpha seeds the max
    g_m[2*n+1] = lrelu(as1 + ad1);
    g_nw[n] = 0.f; g_cnt[n] = 0.f;
}

// ---------------- 4) per-edge: alpha, segment max, enrichment sums ----------------
__global__ void k_edge_max(const int* __restrict__ ei, const float* __restrict__ wgt) {
    int e = blockIdx.x * blockDim.x + threadIdx.x;
    if (e >= EE) return;
    int s = ei[e], d = ei[EE + e];
    float2 as = *(const float2*)(g_asrc + 2 * s);
    float2 ad = *(const float2*)(g_adst + 2 * d);
    float a0 = lrelu(as.x + ad.x);
    float a1 = lrelu(as.y + ad.y);
    *(float2*)(g_ea + 2 * e) = make_float2(a0, a1);
    atomicMaxF(g_m + 2 * d,     a0);
    atomicMaxF(g_m + 2 * d + 1, a1);
    atomicAdd(g_nw + s, wgt[e]);
    atomicAdd(g_cnt + s, 1.0f);
}

// ---------------- 5) per-node: denom init = exp(self_alpha - m) ----------------
__global__ void k_node_denom() {
    int n = blockIdx.x * blockDim.x + threadIdx.x;
    if (n >= NN) return;
    float a0 = lrelu(g_asrc[2*n]   + g_adst[2*n]);
    float a1 = lrelu(g_asrc[2*n+1] + g_adst[2*n+1]);
    g_denom[2*n]   = __expf(a0 - g_m[2*n]);
    g_denom[2*n+1] = __expf(a1 - g_m[2*n+1]);
}

// ---------------- 6) per-edge: e = exp(alpha - m[d]); denom[d] += e ----------------
__global__ void k_edge_denom(const int* __restrict__ ei) {
    int e = blockIdx.x * blockDim.x + threadIdx.x;
    if (e >= EE) return;
    int d = ei[EE + e];
    float2 a = *(const float2*)(g_ea + 2 * e);
    float2 m = *(const float2*)(g_m  + 2 * d);
    float e0 = __expf(a.x - m.x);
    float e1 = __expf(a.y - m.y);
    *(float2*)(g_ea + 2 * e) = make_float2(e0, e1);   // overwrite with exp value
    asm volatile("red.global.add.v2.f32 [%0], {%1,%2};"
                 :: "l"(g_denom + 2 * d), "f"(e0), "f"(e1) : "memory");
}

// ---------------- 7) per-node: out init = p_self*h + bias + enrichment; store 1/denom ----------------
__global__ void k_node_out(float* __restrict__ out, const float* __restrict__ bias,
                           const float* __restrict__ esc) {
    int gid = blockIdx.x * blockDim.x + threadIdx.x;
    int n = gid >> 4;
    if (n >= NN) return;
    int seg  = gid & 15;         // 16 threads / node, float4 each
    int head = seg >> 3;
    float a   = lrelu(g_asrc[2*n+head] + g_adst[2*n+head]);
    float m   = g_m[2*n+head];
    float den = g_denom[2*n+head];
    float rd  = __frcp_rn(den);
    if ((seg & 7) == 0) g_rd[2*n+head] = rd;
    float p = __expf(a - m) * rd;

    float cnt = g_cnt[n];
    float nw  = g_nw[n] / fmaxf(cnt, 1.0f);
    nw = fminf(fmaxf(nw, 0.2f), 5.0f);
    float sf  = 0.1f / (1.0f + __expf(-esc[0]));
    float add = sf * (nw - 1.0f);

    float4 h4 = *(const float4*)(g_h + (size_t)n * HC + seg * 4);
    float4 b4 = ((const float4*)bias)[seg];
    float4 o;
    o.x = p * h4.x + b4.x + add;
    o.y = p * h4.y + b4.y + add;
    o.z = p * h4.z + b4.z + add;
    o.w = p * h4.w + b4.w + add;
    *(float4*)(out + (size_t)n * HC + seg * 4) = o;
}

// ---------------- 8) per-edge scatter: out[d] += p * h[s]  (red.v4) ----------------
__global__ void k_edge_scatter(const int* __restrict__ ei, float* __restrict__ out) {
    int gid = blockIdx.x * blockDim.x + threadIdx.x;
    int e = gid >> 3;
    if (e >= EE) return;
    int seg  = gid & 7;          // 8 threads / edge, 8 floats each
    int head = seg >> 2;
    int s = __ldg(&ei[e]);
    int d = __ldg(&ei[EE + e]);
    float p = g_ea[2 * e + head] * g_rd[2 * d + head];
    const float4* hp = (const float4*)(g_h + (size_t)s * HC + seg * 8);
    float4 h0 = hp[0], h1 = hp[1];
    float* op = out + (size_t)d * HC + seg * 8;
    asm volatile("red.global.add.v4.f32 [%0], {%1,%2,%3,%4};"
                 :: "l"(op), "f"(p*h0.x), "f"(p*h0.y), "f"(p*h0.z), "f"(p*h0.w) : "memory");
    asm volatile("red.global.add.v4.f32 [%0], {%1,%2,%3,%4};"
                 :: "l"(op+4), "f"(p*h1.x), "f"(p*h1.y), "f"(p*h1.z), "f"(p*h1.w) : "memory");
}

extern "C" void kernel_launch(void* const* d_in, const int* in_sizes, int n_in,
                              void* d_out, int out_size) {
    const float* x       = (const float*)d_in[0];
    const int*   ei      = (const int*)  d_in[1];
    const float* wgt     = (const float*)d_in[2];
    const float* W       = (const float*)d_in[3];
    const float* att_src = (const float*)d_in[4];
    const float* att_dst = (const float*)d_in[5];
    const float* bias    = (const float*)d_in[6];
    const float* esc     = (const float*)d_in[7];
    float* out = (float*)d_out;
    (void)in_sizes; (void)n_in; (void)out_size;

    k_elu       <<<(NN * DD / 4 + 255) / 256, 256>>>(x);
    k_gemm      <<<(NN + 63) / 64,            256>>>(W);
    k_node_prep <<<(NN + 255) / 256,          256>>>(att_src, att_dst);
    k_edge_max  <<<(EE + 255) / 256,          256>>>(ei, wgt);
    k_node_denom<<<(NN + 255) / 256,          256>>>();
    k_edge_denom<<<(EE + 255) / 256,          256>>>(ei);
    k_node_out  <<<(NN * 16 + 255) / 256,     256>>>(out, bias, esc);
    k_edge_scatter<<<(EE * 8 + 255) / 256,    256>>>(ei, out);
}

// round 3
// speedup vs baseline: 1.2301x; 1.2301x over previous
#include <cuda_runtime.h>
#include <math.h>

#define NN 50000
#define EE 1600000
#define DD 128
#define HC 64   // H*C = 2*32

// ---- scratch (device globals; no allocation allowed) ----
__device__ float  g_h[NN * HC];        // h = elu(x) @ W          12.8 MB
__device__ float  g_asrc[NN * 2];
__device__ float  g_adst[NN * 2];
__device__ float  g_denom[NN * 2];     // init = exp(self alpha), edges accumulate
__device__ float  g_acc[NN * HC];      // un-normalized output accumulator 12.8 MB
__device__ float2 g_nwcnt[NN];         // {sum w, count} per source node

__device__ __forceinline__ float lrelu(float a) { return a > 0.0f ? a : 0.2f * a; }
__device__ __forceinline__ float elu_f(float v) { return v > 0.0f ? v : (__expf(v) - 1.0f); }

__device__ __forceinline__ void fma4(float4& acc, const float4 wv, const float xs) {
    acc.x += xs * wv.x; acc.y += xs * wv.y; acc.z += xs * wv.z; acc.w += xs * wv.w;
}

// ---------------- 1) h = elu(x) @ W  (W staged in smem, 32KB; elu fused on load) ----------------
__global__ void k_gemm(const float* __restrict__ x, const float* __restrict__ W) {
    __shared__ float sW[DD * HC];                 // [128][64] row-major, 32 KB
    int tid = threadIdx.x;                        // 256 threads
    const float4* Wv = (const float4*)W;
    float4* sWv = (float4*)sW;
#pragma unroll
    for (int i = 0; i < 8; i++) sWv[tid + i * 256] = Wv[tid + i * 256];
    __syncthreads();

    int r  = tid >> 2;                            // 64 rows / block
    int cg = (tid & 3) << 4;                      // 16 cols / thread
    int gr = blockIdx.x * 64 + r;
    if (gr >= NN) return;

    float4 a0 = make_float4(0,0,0,0), a1 = a0, a2 = a0, a3 = a0;
    const float4* xp = (const float4*)(x + (size_t)gr * DD);
#pragma unroll 4
    for (int k4 = 0; k4 < 32; k4++) {
        float4 xv = xp[k4];
        xv.x = elu_f(xv.x); xv.y = elu_f(xv.y); xv.z = elu_f(xv.z); xv.w = elu_f(xv.w);
#pragma unroll
        for (int j = 0; j < 4; j++) {
            float xs = (j == 0) ? xv.x : (j == 1) ? xv.y : (j == 2) ? xv.z : xv.w;
            const float4* wr = (const float4*)&sW[(k4 * 4 + j) * HC + cg];
            fma4(a0, wr[0], xs);
            fma4(a1, wr[1], xs);
            fma4(a2, wr[2], xs);
            fma4(a3, wr[3], xs);
        }
    }
    float4* op = (float4*)(g_h + (size_t)gr * HC + cg);
    op[0] = a0; op[1] = a1; op[2] = a2; op[3] = a3;
}

// ---------------- 2) per-node (one warp/node): a_src, a_dst, self-loop seed ----------------
__global__ void k_node_prep(const float* __restrict__ att_src, const float* __restrict__ att_dst) {
    int warp_in_block = threadIdx.x >> 5;
    int lane = threadIdx.x & 31;
    int n = blockIdx.x * 8 + warp_in_block;
    if (n >= NN) return;

    float h0 = g_h[(size_t)n * HC + lane];        // head 0 channel
    float h1 = g_h[(size_t)n * HC + 32 + lane];   // head 1 channel
    float as0 = h0 * att_src[lane];
    float ad0 = h0 * att_dst[lane];
    float as1 = h1 * att_src[32 + lane];
    float ad1 = h1 * att_dst[32 + lane];
#pragma unroll
    for (int off = 16; off >= 1; off >>= 1) {
        as0 += __shfl_xor_sync(0xffffffff, as0, off);
        ad0 += __shfl_xor_sync(0xffffffff, ad0, off);
        as1 += __shfl_xor_sync(0xffffffff, as1, off);
        ad1 += __shfl_xor_sync(0xffffffff, ad1, off);
    }
    float e0 = __expf(lrelu(as0 + ad0));          // self-loop weight (un-normalized)
    float e1 = __expf(lrelu(as1 + ad1));
    g_acc[(size_t)n * HC + lane]      = e0 * h0;  // seed accumulator with self-loop
    g_acc[(size_t)n * HC + 32 + lane] = e1 * h1;
    if (lane == 0) {
        g_asrc[2*n] = as0; g_asrc[2*n+1] = as1;
        g_adst[2*n] = ad0; g_adst[2*n+1] = ad1;
        g_denom[2*n] = e0; g_denom[2*n+1] = e1;
        g_nwcnt[n] = make_float2(0.0f, 0.0f);
    }
}

// ---------------- 3) single fused edge pass ----------------
// per edge: e = exp(lrelu(asrc[s]+adst[d])); denom[d]+=e; nwcnt[s]+={w,1};
//           acc[d] += e * h[s]   (8 threads/edge, red.v4 x2 each)
__global__ void k_edge_all(const int* __restrict__ ei, const float* __restrict__ wgt) {
    int gid = blockIdx.x * blockDim.x + threadIdx.x;
    int e = gid >> 3;
    if (e >= EE) return;
    int lane = threadIdx.x & 31;
    int sub  = lane & 7;                  // 0..7, 8 floats each

    int s = 0, d = 0; float e0 = 0.f, e1 = 0.f;
    if (sub == 0) {
        s = __ldg(&ei[e]);
        d = __ldg(&ei[EE + e]);
        float2 as = *(const float2*)(g_asrc + 2 * s);
        float2 ad = *(const float2*)(g_adst + 2 * d);
        e0 = __expf(lrelu(as.x + ad.x));
        e1 = __expf(lrelu(as.y + ad.y));
        asm volatile("red.global.add.v2.f32 [%0], {%1,%2};"
                     :: "l"(g_denom + 2 * d), "f"(e0), "f"(e1) : "memory");
        asm volatile("red.global.add.v2.f32 [%0], {%1,%2};"
                     :: "l"((float*)(g_nwcnt + s)), "f"(__ldg(&wgt[e])), "f"(1.0f) : "memory");
    }
    int srcl = lane & ~7;                 // broadcast from octet leader
    s  = __shfl_sync(0xffffffff, s,  srcl);
    d  = __shfl_sync(0xffffffff, d,  srcl);
    e0 = __shfl_sync(0xffffffff, e0, srcl);
    e1 = __shfl_sync(0xffffffff, e1, srcl);

    float ee = (sub >= 4) ? e1 : e0;      // floats [sub*8, sub*8+8): head = sub>>2
    const float4* hp = (const float4*)(g_h + (size_t)s * HC + sub * 8);
    float4 h0 = hp[0], h1 = hp[1];
    float* op = g_acc + (size_t)d * HC + sub * 8;
    asm volatile("red.global.add.v4.f32 [%0], {%1,%2,%3,%4};"
                 :: "l"(op), "f"(ee*h0.x), "f"(ee*h0.y), "f"(ee*h0.z), "f"(ee*h0.w) : "memory");
    asm volatile("red.global.add.v4.f32 [%0], {%1,%2,%3,%4};"
                 :: "l"(op+4), "f"(ee*h1.x), "f"(ee*h1.y), "f"(ee*h1.z), "f"(ee*h1.w) : "memory");
}

// ---------------- 4) per-node: out = acc/denom + bias + enrichment ----------------
__global__ void k_node_out(float* __restrict__ out, const float* __restrict__ bias,
                           const float* __restrict__ esc) {
    int gid = blockIdx.x * blockDim.x + threadIdx.x;
    int n = gid >> 4;
    if (n >= NN) return;
    int seg  = gid & 15;         // 16 threads / node, float4 each
    int head = seg >> 3;
    float rd = __frcp_rn(g_denom[2*n + head]);

    float2 nwc = g_nwcnt[n];
    float nw = nwc.x / fmaxf(nwc.y, 1.0f);
    nw = fminf(fmaxf(nw, 0.2f), 5.0f);
    float sf  = 0.1f / (1.0f + __expf(-esc[0]));
    float add = sf * (nw - 1.0f);

    float4 a4 = *(const float4*)(g_acc + (size_t)n * HC + seg * 4);
    float4 b4 = ((const float4*)bias)[seg];
    float4 o;
    o.x = a4.x * rd + b4.x + add;
    o.y = a4.y * rd + b4.y + add;
    o.z = a4.z * rd + b4.z + add;
    o.w = a4.w * rd + b4.w + add;
    *(float4*)(out + (size_t)n * HC + seg * 4) = o;
}

extern "C" void kernel_launch(void* const* d_in, const int* in_sizes, int n_in,
                              void* d_out, int out_size) {
    const float* x       = (const float*)d_in[0];
    const int*   ei      = (const int*)  d_in[1];
    const float* wgt     = (const float*)d_in[2];
    const float* W       = (const float*)d_in[3];
    const float* att_src = (const float*)d_in[4];
    const float* att_dst = (const float*)d_in[5];
    const float* bias    = (const float*)d_in[6];
    const float* esc     = (const float*)d_in[7];
    float* out = (float*)d_out;
    (void)in_sizes; (void)n_in; (void)out_size;

    k_gemm      <<<(NN + 63) / 64,        256>>>(x, W);
    k_node_prep <<<(NN + 7) / 8,          256>>>(att_src, att_dst);
    k_edge_all  <<<(EE * 8 + 255) / 256,  256>>>(ei, wgt);
    k_node_out  <<<(NN * 16 + 255) / 256, 256>>>(out, bias, esc);
}

// round 4
// speedup vs baseline: 1.3806x; 1.1224x over previous
#include <cuda_runtime.h>
#include <math.h>

#define NN 50000
#define EE 1600000
#define DD 128
#define HC 64     // H*C = 2*32
#define NB 196    // ceil(NN/256) scan blocks

// ---- scratch (device globals; no allocation allowed) ----
__device__ float  g_h[NN * HC];        // h = elu(x) @ W          12.8 MB
__device__ float  g_asrc[NN * 2];
__device__ float  g_adst[NN * 2];
__device__ float2 g_nwcnt[NN];         // {sum w, count} per source node
__device__ int    g_deg[NN];           // in-degree (excl self loop)
__device__ int    g_off[NN];           // exclusive prefix of deg
__device__ int    g_cursor[NN];        // scatter cursors (copy of g_off)
__device__ int    g_bsum[256];         // per-block scan sums
__device__ int    g_bsumx[256];        // exclusive-scanned block sums
__device__ float4 g_sorted[EE];        // {src(asint), e0, e1, pad}  25.6 MB

__device__ __forceinline__ float lrelu(float a) { return a > 0.0f ? a : 0.2f * a; }
__device__ __forceinline__ float elu_f(float v) { return v > 0.0f ? v : (__expf(v) - 1.0f); }

__device__ __forceinline__ void fma4(float4& acc, const float4 wv, const float xs) {
    acc.x += xs * wv.x; acc.y += xs * wv.y; acc.z += xs * wv.z; acc.w += xs * wv.w;
}

// ---------------- 1) h = elu(x) @ W  (W staged in smem; elu fused on load) ----------------
__global__ void k_gemm(const float* __restrict__ x, const float* __restrict__ W) {
    __shared__ float sW[DD * HC];                 // 32 KB
    int tid = threadIdx.x;                        // 256 threads
    const float4* Wv = (const float4*)W;
    float4* sWv = (float4*)sW;
#pragma unroll
    for (int i = 0; i < 8; i++) sWv[tid + i * 256] = Wv[tid + i * 256];
    __syncthreads();

    int r  = tid >> 2;                            // 64 rows / block
    int cg = (tid & 3) << 4;                      // 16 cols / thread
    int gr = blockIdx.x * 64 + r;
    if (gr >= NN) return;

    float4 a0 = make_float4(0,0,0,0), a1 = a0, a2 = a0, a3 = a0;
    const float4* xp = (const float4*)(x + (size_t)gr * DD);
#pragma unroll 4
    for (int k4 = 0; k4 < 32; k4++) {
        float4 xv = xp[k4];
        xv.x = elu_f(xv.x); xv.y = elu_f(xv.y); xv.z = elu_f(xv.z); xv.w = elu_f(xv.w);
#pragma unroll
        for (int j = 0; j < 4; j++) {
            float xs = (j == 0) ? xv.x : (j == 1) ? xv.y : (j == 2) ? xv.z : xv.w;
            const float4* wr = (const float4*)&sW[(k4 * 4 + j) * HC + cg];
            fma4(a0, wr[0], xs);
            fma4(a1, wr[1], xs);
            fma4(a2, wr[2], xs);
            fma4(a3, wr[3], xs);
        }
    }
    float4* op = (float4*)(g_h + (size_t)gr * HC + cg);
    op[0] = a0; op[1] = a1; op[2] = a2; op[3] = a3;
}

// ---------------- 2) per-node (one warp/node): a_src, a_dst; zero counters ----------------
__global__ void k_node_prep(const float* __restrict__ att_src, const float* __restrict__ att_dst) {
    int warp_in_block = threadIdx.x >> 5;
    int lane = threadIdx.x & 31;
    int n = blockIdx.x * 8 + warp_in_block;
    if (n >= NN) return;

    float h0 = g_h[(size_t)n * HC + lane];
    float h1 = g_h[(size_t)n * HC + 32 + lane];
    float as0 = h0 * att_src[lane];
    float ad0 = h0 * att_dst[lane];
    float as1 = h1 * att_src[32 + lane];
    float ad1 = h1 * att_dst[32 + lane];
#pragma unroll
    for (int off = 16; off >= 1; off >>= 1) {
        as0 += __shfl_xor_sync(0xffffffff, as0, off);
        ad0 += __shfl_xor_sync(0xffffffff, ad0, off);
        as1 += __shfl_xor_sync(0xffffffff, as1, off);
        ad1 += __shfl_xor_sync(0xffffffff, ad1, off);
    }
    if (lane == 0) {
        g_asrc[2*n] = as0; g_asrc[2*n+1] = as1;
        g_adst[2*n] = ad0; g_adst[2*n+1] = ad1;
        g_nwcnt[n] = make_float2(0.0f, 0.0f);
        g_deg[n] = 0;
    }
}

// ---------------- 3) histogram: deg[dst]++, nwcnt[src] += {w,1} ----------------
__global__ void k_hist(const int* __restrict__ ei, const float* __restrict__ wgt) {
    int e = blockIdx.x * blockDim.x + threadIdx.x;
    if (e >= EE) return;
    int s = __ldg(&ei[e]);
    int d = __ldg(&ei[EE + e]);
    atomicAdd(&g_deg[d], 1);
    float w = __ldg(&wgt[e]);
    asm volatile("red.global.add.v2.f32 [%0], {%1,%2};"
                 :: "l"((float*)(g_nwcnt + s)), "f"(w), "f"(1.0f) : "memory");
}

// ---------------- 4) three-step exclusive scan of deg -> off ----------------
__global__ void k_scan1() {
    __shared__ int tmp[256];
    int tid = threadIdx.x;
    int i = blockIdx.x * 256 + tid;
    int v = (i < NN) ? g_deg[i] : 0;
    tmp[tid] = v;
    __syncthreads();
#pragma unroll
    for (int off = 1; off < 256; off <<= 1) {
        int t = (tid >= off) ? tmp[tid - off] : 0;
        __syncthreads();
        tmp[tid] += t;
        __syncthreads();
    }
    if (i < NN) g_off[i] = tmp[tid] - v;
    if (tid == 255) g_bsum[blockIdx.x] = tmp[255];
}
__global__ void k_scan2() {
    __shared__ int tmp[256];
    int tid = threadIdx.x;
    int v = (tid < NB) ? g_bsum[tid] : 0;
    tmp[tid] = v;
    __syncthreads();
#pragma unroll
    for (int off = 1; off < 256; off <<= 1) {
        int t = (tid >= off) ? tmp[tid - off] : 0;
        __syncthreads();
        tmp[tid] += t;
        __syncthreads();
    }
    if (tid < NB) g_bsumx[tid] = tmp[tid] - v;
}
__global__ void k_scan3() {
    int i = blockIdx.x * 256 + threadIdx.x;
    if (i >= NN) return;
    int o = g_off[i] + g_bsumx[blockIdx.x];
    g_off[i] = o;
    g_cursor[i] = o;
}

// ---------------- 5) scatter: packed {src, e0, e1} records sorted by dst ----------------
__global__ void k_scatter(const int* __restrict__ ei) {
    int e = blockIdx.x * blockDim.x + threadIdx.x;
    if (e >= EE) return;
    int s = __ldg(&ei[e]);
    int d = __ldg(&ei[EE + e]);
    float2 as = *(const float2*)(g_asrc + 2 * s);
    float2 ad = *(const float2*)(g_adst + 2 * d);
    float e0 = __expf(lrelu(as.x + ad.x));
    float e1 = __expf(lrelu(as.y + ad.y));
    int pos = atomicAdd(&g_cursor[d], 1);
    g_sorted[pos] = make_float4(__int_as_float(s), e0, e1, 0.0f);
}

// ---------------- 6) gather: one warp per dst node, register accumulation ----------------
__global__ void k_gather(float* __restrict__ out, const float* __restrict__ bias,
                         const float* __restrict__ esc) {
    int warp_in_block = threadIdx.x >> 5;
    int lane = threadIdx.x & 31;
    int n = blockIdx.x * 8 + warp_in_block;
    if (n >= NN) return;

    int head = lane >> 4;                 // lanes 0-15: head0 ch, 16-31: head1
    int start = g_off[n];
    int cnt   = g_deg[n];

    float2 acc = make_float2(0.0f, 0.0f);
    float den = 0.0f;

    int j = 0;
    for (; j + 2 <= cnt; j += 2) {
        float4 r0 = __ldg(&g_sorted[start + j]);
        float4 r1 = __ldg(&g_sorted[start + j + 1]);
        int   s0 = __float_as_int(r0.x);
        int   s1 = __float_as_int(r1.x);
        float ee0 = head ? r0.z : r0.y;
        float ee1 = head ? r1.z : r1.y;
        float2 h0 = *(const float2*)(g_h + (size_t)s0 * HC + 2 * lane);
        float2 h1 = *(const float2*)(g_h + (size_t)s1 * HC + 2 * lane);
        acc.x += ee0 * h0.x; acc.y += ee0 * h0.y;
        acc.x += ee1 * h1.x; acc.y += ee1 * h1.y;
        den += ee0 + ee1;
    }
    if (j < cnt) {
        float4 r0 = __ldg(&g_sorted[start + j]);
        int   s0 = __float_as_int(r0.x);
        float ee0 = head ? r0.z : r0.y;
        float2 h0 = *(const float2*)(g_h + (size_t)s0 * HC + 2 * lane);
        acc.x += ee0 * h0.x; acc.y += ee0 * h0.y;
        den += ee0;
    }

    // self loop
    float a_self = lrelu(g_asrc[2*n + head] + g_adst[2*n + head]);
    float e_self = __expf(a_self);
    float2 hs = *(const float2*)(g_h + (size_t)n * HC + 2 * lane);
    acc.x += e_self * hs.x; acc.y += e_self * hs.y;
    den += e_self;

    float rd = __frcp_rn(den);

    // enrichment
    float2 nwc = g_nwcnt[n];
    float nw = nwc.x / fmaxf(nwc.y, 1.0f);
    nw = fminf(fmaxf(nw, 0.2f), 5.0f);
    float sf  = 0.1f / (1.0f + __expf(-esc[0]));
    float add = sf * (nw - 1.0f);

    float2 b2 = *(const float2*)(bias + 2 * lane);
    float2 o;
    o.x = acc.x * rd + b2.x + add;
    o.y = acc.y * rd + b2.y + add;
    *(float2*)(out + (size_t)n * HC + 2 * lane) = o;
}

extern "C" void kernel_launch(void* const* d_in, const int* in_sizes, int n_in,
                              void* d_out, int out_size) {
    const float* x       = (const float*)d_in[0];
    const int*   ei      = (const int*)  d_in[1];
    const float* wgt     = (const float*)d_in[2];
    const float* W       = (const float*)d_in[3];
    const float* att_src = (const float*)d_in[4];
    const float* att_dst = (const float*)d_in[5];
    const float* bias    = (const float*)d_in[6];
    const float* esc     = (const float*)d_in[7];
    float* out = (float*)d_out;
    (void)in_sizes; (void)n_in; (void)out_size;

    k_gemm      <<<(NN + 63) / 64,       256>>>(x, W);
    k_node_prep <<<(NN + 7) / 8,         256>>>(att_src, att_dst);
    k_hist      <<<(EE + 255) / 256,     256>>>(ei, wgt);
    k_scan1     <<<NB,                   256>>>();
    k_scan2     <<<1,                    256>>>();
    k_scan3     <<<NB,                   256>>>();
    k_scatter   <<<(EE + 255) / 256,     256>>>(ei);
    k_gather    <<<(NN + 7) / 8,         256>>>(out, bias, esc);
}